// round 14
// baseline (speedup 1.0000x reference)
#include <cuda_runtime.h>
#include <cuda_bf16.h>
#include <cstdint>

#define HH   128
#define WW   128
#define NMAX 16384
#define NSPLIT 32
#define KSLICE (NMAX / NSPLIT)       /* 512 */
#define KCHUNK 64
#define NCHUNK (KSLICE / KCHUNK)     /* 8 */
#define FXc 128.0f
#define FYc 128.0f
#define CXc 64.0f
#define CYc 64.0f
#define EPSc 1e-8f

// ---------------- static device scratch (no allocation allowed) -------------
__device__ __nv_bfloat16 d_A[(size_t)128 * NMAX];
__device__ __nv_bfloat16 d_B[(size_t)512 * NMAX];
__device__ float         d_Part[NSPLIT][128][512];   // split-K partials (8 MB)

// ---------------- PTX helpers ------------------------------------------------
__device__ __forceinline__ uint32_t smem_u32(const void* p) {
    uint32_t a;
    asm("{ .reg .u64 t; cvta.to.shared.u64 t, %1; cvt.u32.u64 %0, t; }" : "=r"(a) : "l"(p));
    return a;
}
#define LDSM4(r0, r1, r2, r3, addr)                                          \
    asm volatile("ldmatrix.sync.aligned.m8n8.x4.shared.b16 {%0,%1,%2,%3}, [%4];" \
        : "=r"(r0), "=r"(r1), "=r"(r2), "=r"(r3) : "r"(addr))
#define MMA16816(d, a, b)                                                    \
    asm volatile("mma.sync.aligned.m16n8k16.row.col.f32.bf16.bf16.f32 "      \
        "{%0,%1,%2,%3}, {%4,%5,%6,%7}, {%8,%9}, {%0,%1,%2,%3};"              \
        : "+f"((d)[0]), "+f"((d)[1]), "+f"((d)[2]), "+f"((d)[3])             \
        : "r"((a)[0]), "r"((a)[1]), "r"((a)[2]), "r"((a)[3]),                \
          "r"((b)[0]), "r"((b)[1]))
#define CPASYNC16(so, src)                                                   \
    asm volatile("cp.async.cg.shared.global [%0], [%1], 16;"                 \
        :: "r"(so), "l"(src) : "memory")
#define MULBF2(res, a, b) \
    asm("mul.bf16x2 %0, %1, %2;" : "=r"(res) : "r"(a), "r"(b))

// packed f32x2 helpers
__device__ __forceinline__ unsigned long long f2pack(float a, float b) {
    unsigned long long r;
    asm("mov.b64 %0, {%1, %2};" : "=l"(r) : "f"(a), "f"(b));
    return r;
}
__device__ __forceinline__ void f2unpack(unsigned long long v, float& a, float& b) {
    asm("mov.b64 {%0, %1}, %2;" : "=f"(a), "=f"(b) : "l"(v));
}
__device__ __forceinline__ unsigned long long f2mul(unsigned long long a, unsigned long long b) {
    unsigned long long r;
    asm("mul.rn.f32x2 %0, %1, %2;" : "=l"(r) : "l"(a), "l"(b));
    return r;
}

// swizzled smem byte offset for 128B rows (64 bf16), 16B-unit column c (0..7)
__device__ __forceinline__ uint32_t swz64(int r, int c) {
    return (uint32_t)((r << 7) + ((((c) ^ (r)) & 7) << 4));
}

__device__ __forceinline__ uint32_t pkbf(float a, float b) {
    __nv_bfloat162 h = __floats2bfloat162_rn(a, b);
    uint32_t u;
    memcpy(&u, &h, 4);
    return u;
}

// ---------------- prep v4: shared preamble + packed math + STG.128 ----------
__global__ void __launch_bounds__(512) prep_kernel(
    const float* __restrict__ pos, const float* __restrict__ col,
    const float* __restrict__ opa, const float* __restrict__ sca,
    const float* __restrict__ qv,  const float* __restrict__ tv)
{
    __shared__ float sPx[128], sPy[128], sEe[128], sQ2[128];
    __shared__ float sCr[128], sCg[128], sCb[128], sOo[128];

    const int tid = threadIdx.x;

    if (tid < 128) {
        int g = blockIdx.x * 128 + tid;
        float qw = qv[0], qx = qv[1], qy = qv[2], qz = qv[3];
        float qn = rsqrtf(qw * qw + qx * qx + qy * qy + qz * qz);
        qw *= qn; qx *= qn; qy *= qn; qz *= qn;
        float r00 = 1.f - 2.f * (qy * qy + qz * qz), r01 = 2.f * (qx * qy - qz * qw), r02 = 2.f * (qx * qz + qy * qw);
        float r10 = 2.f * (qx * qy + qz * qw), r11 = 1.f - 2.f * (qx * qx + qz * qz), r12 = 2.f * (qy * qz - qx * qw);
        float r20 = 2.f * (qx * qz - qy * qw), r21 = 2.f * (qy * qz + qx * qw), r22 = 1.f - 2.f * (qx * qx + qy * qy);

        float p0 = pos[3 * g + 0], p1 = pos[3 * g + 1], p2 = pos[3 * g + 2];
        float cx = r00 * p0 + r01 * p1 + r02 * p2 + tv[0];
        float cy = r10 * p0 + r11 * p1 + r12 * p2 + tv[1];
        float cz = r20 * p0 + r21 * p1 + r22 * p2 + tv[2];
        float invz = __fdividef(1.f, cz);
        sPx[tid] = cx * invz * FXc + CXc;
        sPy[tid] = cy * invz * FYc + CYc;
        float s = sca[g];
        float e = -0.5f * __fdividef(1.f, s * s);
        sEe[tid] = e;
        sQ2[tid] = __expf(2.f * e);
        float o = opa[g];
        sOo[tid] = o;
        sCr[tid] = o * col[3 * g + 0];
        sCg[tid] = o * col[3 * g + 1];
        sCb[tid] = o * col[3 * g + 2];
    }
    __syncthreads();

    const int oct = tid & 15;
    const int seg = tid >> 4;            // 0..31 -> 4-px segment
    const int gl  = oct * 8;             // local gaussian base (8 per thread)
    const int g0  = blockIdx.x * 128 + gl;
    const int pb  = seg * 4;

    float e[8], px[8], py[8];
    #pragma unroll
    for (int j = 0; j < 8; ++j) {
        e[j]  = sEe[gl + j];
        px[j] = sPx[gl + j];
        py[j] = sPy[gl + j];
    }
    unsigned long long q[4];
    uint32_t cr[4], cg[4], cb[4], oo[4];
    #pragma unroll
    for (int j = 0; j < 4; ++j) {
        q[j]  = f2pack(sQ2[gl + 2 * j], sQ2[gl + 2 * j + 1]);
        cr[j] = pkbf(sCr[gl + 2 * j], sCr[gl + 2 * j + 1]);
        cg[j] = pkbf(sCg[gl + 2 * j], sCg[gl + 2 * j + 1]);
        cb[j] = pkbf(sCb[gl + 2 * j], sCb[gl + 2 * j + 1]);
        oo[j] = pkbf(sOo[gl + 2 * j], sOo[gl + 2 * j + 1]);
    }

    // ---- B rows for this segment's 4 x-values (uint4 per channel-row) ----
    {
        unsigned long long t[4], u[4];
        #pragma unroll
        for (int j = 0; j < 4; ++j) {
            float da = (float)pb - px[2 * j], db = (float)pb - px[2 * j + 1];
            t[j] = f2pack(__expf(e[2 * j] * da * da), __expf(e[2 * j + 1] * db * db));
            u[j] = f2pack(__expf(e[2 * j] * (2.f * da + 1.f)),
                          __expf(e[2 * j + 1] * (2.f * db + 1.f)));
        }
        __nv_bfloat16* bp = d_B + (size_t)pb * NMAX + g0;
        #pragma unroll
        for (int k = 0; k < 4; ++k) {
            uint32_t p[4];
            #pragma unroll
            for (int j = 0; j < 4; ++j) {
                float a0, a1;
                f2unpack(t[j], a0, a1);
                p[j] = pkbf(a0, a1);
            }
            uint4 v;
            MULBF2(v.x, p[0], cr[0]); MULBF2(v.y, p[1], cr[1]);
            MULBF2(v.z, p[2], cr[2]); MULBF2(v.w, p[3], cr[3]);
            *reinterpret_cast<uint4*>(bp + (size_t)0 * 128 * NMAX) = v;
            MULBF2(v.x, p[0], cg[0]); MULBF2(v.y, p[1], cg[1]);
            MULBF2(v.z, p[2], cg[2]); MULBF2(v.w, p[3], cg[3]);
            *reinterpret_cast<uint4*>(bp + (size_t)1 * 128 * NMAX) = v;
            MULBF2(v.x, p[0], cb[0]); MULBF2(v.y, p[1], cb[1]);
            MULBF2(v.z, p[2], cb[2]); MULBF2(v.w, p[3], cb[3]);
            *reinterpret_cast<uint4*>(bp + (size_t)2 * 128 * NMAX) = v;
            MULBF2(v.x, p[0], oo[0]); MULBF2(v.y, p[1], oo[1]);
            MULBF2(v.z, p[2], oo[2]); MULBF2(v.w, p[3], oo[3]);
            *reinterpret_cast<uint4*>(bp + (size_t)3 * 128 * NMAX) = v;
            #pragma unroll
            for (int j = 0; j < 4; ++j) { t[j] = f2mul(t[j], u[j]); u[j] = f2mul(u[j], q[j]); }
            bp += NMAX;
        }
    }
    // ---- A rows for this segment's 4 y-values ----
    {
        unsigned long long t[4], u[4];
        #pragma unroll
        for (int j = 0; j < 4; ++j) {
            float da = (float)pb - py[2 * j], db = (float)pb - py[2 * j + 1];
            t[j] = f2pack(__expf(e[2 * j] * da * da), __expf(e[2 * j + 1] * db * db));
            u[j] = f2pack(__expf(e[2 * j] * (2.f * da + 1.f)),
                          __expf(e[2 * j + 1] * (2.f * db + 1.f)));
        }
        __nv_bfloat16* ap = d_A + (size_t)pb * NMAX + g0;
        #pragma unroll
        for (int k = 0; k < 4; ++k) {
            uint4 v;
            float a0, a1;
            f2unpack(t[0], a0, a1); v.x = pkbf(a0, a1);
            f2unpack(t[1], a0, a1); v.y = pkbf(a0, a1);
            f2unpack(t[2], a0, a1); v.z = pkbf(a0, a1);
            f2unpack(t[3], a0, a1); v.w = pkbf(a0, a1);
            *reinterpret_cast<uint4*>(ap) = v;
            #pragma unroll
            for (int j = 0; j < 4; ++j) { t[j] = f2mul(t[j], u[j]); u[j] = f2mul(u[j], q[j]); }
            ap += NMAX;
        }
    }
}

// ---------------- GEMM via HMMA, 4-stage pipeline ---------------------------
// grid = (4 N-tiles, 32 K-splits) = 128 CTAs. Block = 512 threads (16 warps,
// 4M x 4N). Stage = 32KB: A[128x64] 16KB + B[128x64] 16KB. 4 stages = 128KB.
#define STAGE_BYTES 32768
#define SM_B_OFF 16384
#define SMEM_TOTAL 131072

__global__ void __launch_bounds__(512, 1) gemm_kernel()
{
    extern __shared__ char smem[];
    const uint32_t sb = smem_u32(smem);
    const int tid  = threadIdx.x;
    const int lane = tid & 31;
    const int wid  = tid >> 5;           // 0..15
    const int wm   = (wid & 3) * 32;     // warp M offset
    const int wn   = (wid >> 2) * 32;    // warp N offset
    const int ntb  = blockIdx.x * 128;   // N-tile base row in B table
    const int g0   = blockIdx.y * KSLICE;

    float acc[2][4][4];
    #pragma unroll
    for (int mf = 0; mf < 2; ++mf)
        #pragma unroll
        for (int nf = 0; nf < 4; ++nf)
            #pragma unroll
            for (int q = 0; q < 4; ++q) acc[mf][nf][q] = 0.f;

    const int matA = lane >> 3;
    const int arow = (lane & 7) + ((matA & 1) << 3);
    const int acadd = matA >> 1;
    const int brow = (lane & 7) + ((matA >> 1) << 3);
    const int bcadd = matA & 1;

    // load chunk into stage s: 1024 A + 1024 B 16B-chunks, 4/thread
    auto load_chunk = [&](int s, int ck) {
        const int kb = g0 + ck * KCHUNK;
        const uint32_t st = sb + s * STAGE_BYTES;
        #pragma unroll
        for (int it = 0; it < 4; ++it) {
            int i = it * 512 + tid;            // 0..2047
            if (i < 1024) {
                int r = i >> 3, c = i & 7;
                const void* src = (const void*)(d_A + (size_t)r * NMAX + kb + c * 8);
                CPASYNC16(st + swz64(r, c), src);
            } else {
                int j = i - 1024;
                int r = j >> 3, c = j & 7;
                const void* src = (const void*)(d_B + (size_t)(ntb + r) * NMAX + kb + c * 8);
                CPASYNC16(st + SM_B_OFF + swz64(r, c), src);
            }
        }
        asm volatile("cp.async.commit_group;" ::: "memory");
    };

    // prologue: 3 chunks in flight
    load_chunk(0, 0);
    load_chunk(1, 1);
    load_chunk(2, 2);

    #pragma unroll
    for (int ck = 0; ck < NCHUNK; ++ck) {
        if (ck < NCHUNK - 2)
            asm volatile("cp.async.wait_group 2;" ::: "memory");
        else if (ck == NCHUNK - 2)
            asm volatile("cp.async.wait_group 1;" ::: "memory");
        else
            asm volatile("cp.async.wait_group 0;" ::: "memory");
        __syncthreads();

        if (ck + 3 < NCHUNK) load_chunk((ck + 3) & 3, ck + 3);

        const uint32_t st = sb + (ck & 3) * STAGE_BYTES;
        #pragma unroll
        for (int ks = 0; ks < 4; ++ks) {
            const int c0 = ks * 2;
            uint32_t a[2][4];
            #pragma unroll
            for (int mf = 0; mf < 2; ++mf)
                LDSM4(a[mf][0], a[mf][1], a[mf][2], a[mf][3],
                      st + swz64(wm + mf * 16 + arow, c0 + acadd));
            uint32_t b[4][2];
            #pragma unroll
            for (int bq = 0; bq < 2; ++bq) {
                uint32_t r0, r1, r2, r3;
                LDSM4(r0, r1, r2, r3,
                      st + SM_B_OFF + swz64(wn + bq * 16 + brow, c0 + bcadd));
                b[2 * bq][0] = r0; b[2 * bq][1] = r1;
                b[2 * bq + 1][0] = r2; b[2 * bq + 1][1] = r3;
            }
            #pragma unroll
            for (int mf = 0; mf < 2; ++mf)
                #pragma unroll
                for (int nf = 0; nf < 4; ++nf)
                    MMA16816(acc[mf][nf], a[mf], b[nf]);
        }
    }

    // ---- store 128x128 fp32 partial for this split
    float* part = &d_Part[blockIdx.y][0][0];
    #pragma unroll
    for (int mf = 0; mf < 2; ++mf) {
        #pragma unroll
        for (int nf = 0; nf < 4; ++nf) {
            int row = wm + mf * 16 + (lane >> 2);
            int cc  = ntb + wn + nf * 8 + (lane & 3) * 2;
            float2 v0 = make_float2(acc[mf][nf][0], acc[mf][nf][1]);
            float2 v1 = make_float2(acc[mf][nf][2], acc[mf][nf][3]);
            *reinterpret_cast<float2*>(part + (size_t)row * 512 + cc)       = v0;
            *reinterpret_cast<float2*>(part + (size_t)(row + 8) * 512 + cc) = v1;
        }
    }
}

// ---------------- finalize: reduce splits, divide, tile-scatter --------------
__global__ void __launch_bounds__(256) finalize_kernel(
    float* __restrict__ out, const int* __restrict__ tileHW,
    const int* __restrict__ chunkG, int N)
{
    int p = blockIdx.x * blockDim.x + threadIdx.x;
    if (p >= HH * WW) return;
    int y = p >> 7, x = p & 127;

    float r = 0.f, g = 0.f, b = 0.f, d = 0.f;
    #pragma unroll
    for (int s = 0; s < NSPLIT; ++s) {
        r += d_Part[s][y][x];
        g += d_Part[s][y][128 + x];
        b += d_Part[s][y][256 + x];
        d += d_Part[s][y][384 + x];
    }

    int cg = chunkG[0];
    if (cg <= 0 || cg > N) cg = N;
    d += (float)(N / cg) * EPSc;

    int tw = tileHW[0];
    if (tw <= 0 || tw > 128) tw = 64;
    int step = tw * tw;
    int t = p / step;
    int q = p - t * step;

    float inv = __fdividef(1.f, d);
    float* o = out + (size_t)t * 3 * step + q;
    o[0]        = r * inv;
    o[step]     = g * inv;
    o[2 * step] = b * inv;
}

// ---------------- launch -----------------------------------------------------
extern "C" void kernel_launch(void* const* d_in, const int* in_sizes, int n_in,
                              void* d_out, int out_size)
{
    const float* pos = (const float*)d_in[0];
    const float* col = (const float*)d_in[1];
    const float* opa = (const float*)d_in[2];
    const float* sca = (const float*)d_in[3];
    const float* qv  = (const float*)d_in[4];
    const float* tv  = (const float*)d_in[5];
    const int*   tHW = (n_in > 6) ? (const int*)d_in[6] : nullptr;
    const int*   cG  = (n_in > 7) ? (const int*)d_in[7] : nullptr;

    int N = in_sizes[0] / 3;
    if (N > NMAX) N = NMAX;

    prep_kernel<<<NMAX / 128, 512>>>(pos, col, opa, sca, qv, tv);

    cudaFuncSetAttribute(gemm_kernel, cudaFuncAttributeMaxDynamicSharedMemorySize, SMEM_TOTAL);
    gemm_kernel<<<dim3(4, NSPLIT), 512, SMEM_TOTAL>>>();

    finalize_kernel<<<(HH * WW + 255) / 256, 256>>>((float*)d_out, tHW, cG, N);
}

// round 15
// speedup vs baseline: 1.1216x; 1.1216x over previous
#include <cuda_runtime.h>
#include <cuda_bf16.h>
#include <cstdint>

#define HH   128
#define WW   128
#define NMAX 16384
#define NSPLIT 32
#define KSLICE (NMAX / NSPLIT)       /* 512 */
#define FXc 128.0f
#define FYc 128.0f
#define CXc 64.0f
#define CYc 64.0f
#define EPSc 1e-8f

// ---------------- static device scratch (no allocation allowed) -------------
// split-K partials; column layout n = x*4 + ch (channels interleaved)
__device__ float d_Part[NSPLIT][128][512];

// ---------------- PTX helpers ------------------------------------------------
__device__ __forceinline__ uint32_t smem_u32(const void* p) {
    uint32_t a;
    asm("{ .reg .u64 t; cvta.to.shared.u64 t, %1; cvt.u32.u64 %0, t; }" : "=r"(a) : "l"(p));
    return a;
}
#define LDSM4(r0, r1, r2, r3, addr)                                          \
    asm volatile("ldmatrix.sync.aligned.m8n8.x4.shared.b16 {%0,%1,%2,%3}, [%4];" \
        : "=r"(r0), "=r"(r1), "=r"(r2), "=r"(r3) : "r"(addr))
#define MMA16816(d, a, b)                                                    \
    asm volatile("mma.sync.aligned.m16n8k16.row.col.f32.bf16.bf16.f32 "      \
        "{%0,%1,%2,%3}, {%4,%5,%6,%7}, {%8,%9}, {%0,%1,%2,%3};"              \
        : "+f"((d)[0]), "+f"((d)[1]), "+f"((d)[2]), "+f"((d)[3])             \
        : "r"((a)[0]), "r"((a)[1]), "r"((a)[2]), "r"((a)[3]),                \
          "r"((b)[0]), "r"((b)[1]))
#define MULBF2(res, a, b) \
    asm("mul.bf16x2 %0, %1, %2;" : "=r"(res) : "r"(a), "r"(b))
#define STS32(addr, v) \
    asm volatile("st.shared.b32 [%0], %1;" :: "r"(addr), "r"(v))

// packed f32x2 helpers
__device__ __forceinline__ unsigned long long f2pack(float a, float b) {
    unsigned long long r;
    asm("mov.b64 %0, {%1, %2};" : "=l"(r) : "f"(a), "f"(b));
    return r;
}
__device__ __forceinline__ void f2unpack(unsigned long long v, float& a, float& b) {
    asm("mov.b64 {%0, %1}, %2;" : "=f"(a), "=f"(b) : "l"(v));
}
__device__ __forceinline__ unsigned long long f2mul(unsigned long long a, unsigned long long b) {
    unsigned long long r;
    asm("mul.rn.f32x2 %0, %1, %2;" : "=l"(r) : "l"(a), "l"(b));
    return r;
}

// swizzled smem byte offset: 256B rows (128 bf16), granule c = 16B unit 0..15
__device__ __forceinline__ uint32_t swz(int r, int c) {
    return (uint32_t)(r * 256 + ((((c) & 8) | (((c) ^ (r)) & 7)) << 4));
}
// swizzled byte address of the bf16 PAIR starting at even g-index gp in row r
__device__ __forceinline__ uint32_t swzg(int r, int gp) {
    int c = gp >> 3;
    return (uint32_t)(r * 256 + (((c & 8) | ((c ^ r) & 7)) << 4) + ((gp * 2) & 15));
}

__device__ __forceinline__ uint32_t pkbf(float a, float b) {
    __nv_bfloat162 h = __floats2bfloat162_rn(a, b);
    uint32_t u;
    memcpy(&u, &h, 4);
    return u;
}

// ---------------- fused prep+GEMM mega-kernel -------------------------------
// grid = (4 N-tiles, 32 K-splits) = 128 CTAs, 512 threads (16 warps, 4Mx4N).
// N-tile t covers n=[128t,128t+128) = x in [32t,32t+32), channels interleaved.
// Per 128-gaussian chunk: fill A[128y x 128g] + B[128n x 128g] bf16 tiles in
// smem directly (no global tables), then 8 k16 HMMA steps.
#define SM_B_OFF 32768
#define SMEM_TOTAL 65536

__global__ void __launch_bounds__(512, 1) mega_kernel(
    const float* __restrict__ pos, const float* __restrict__ col,
    const float* __restrict__ opa, const float* __restrict__ sca,
    const float* __restrict__ qv,  const float* __restrict__ tv)
{
    __shared__ float sPx[512], sPy[512], sEe[512], sQ2[512];
    __shared__ float sWr[512], sWg[512], sWb[512], sWo[512];
    extern __shared__ char smem[];
    const uint32_t sb = smem_u32(smem);
    const int tid  = threadIdx.x;
    const int lane = tid & 31;
    const int wid  = tid >> 5;
    const int wm   = (wid & 3) * 32;
    const int wn   = (wid >> 2) * 32;
    const int ntb  = blockIdx.x * 128;   // global n base
    const int x0b  = blockIdx.x * 32;    // global x base for this N-tile
    const int g0   = blockIdx.y * KSLICE;

    // ---- params: one gaussian per thread ----
    {
        int g = g0 + tid;
        float qw = qv[0], qx = qv[1], qy = qv[2], qz = qv[3];
        float qn = rsqrtf(qw * qw + qx * qx + qy * qy + qz * qz);
        qw *= qn; qx *= qn; qy *= qn; qz *= qn;
        float r00 = 1.f - 2.f * (qy * qy + qz * qz), r01 = 2.f * (qx * qy - qz * qw), r02 = 2.f * (qx * qz + qy * qw);
        float r10 = 2.f * (qx * qy + qz * qw), r11 = 1.f - 2.f * (qx * qx + qz * qz), r12 = 2.f * (qy * qz - qx * qw);
        float r20 = 2.f * (qx * qz - qy * qw), r21 = 2.f * (qy * qz + qx * qw), r22 = 1.f - 2.f * (qx * qx + qy * qy);

        float p0 = pos[3 * g + 0], p1 = pos[3 * g + 1], p2 = pos[3 * g + 2];
        float cx = r00 * p0 + r01 * p1 + r02 * p2 + tv[0];
        float cy = r10 * p0 + r11 * p1 + r12 * p2 + tv[1];
        float cz = r20 * p0 + r21 * p1 + r22 * p2 + tv[2];
        float invz = __fdividef(1.f, cz);
        sPx[tid] = cx * invz * FXc + CXc;
        sPy[tid] = cy * invz * FYc + CYc;
        float s = sca[g];
        float e = -0.5f * __fdividef(1.f, s * s);
        sEe[tid] = e;
        sQ2[tid] = __expf(2.f * e);
        float o = opa[g];
        sWo[tid] = o;
        sWr[tid] = o * col[3 * g + 0];
        sWg[tid] = o * col[3 * g + 1];
        sWb[tid] = o * col[3 * g + 2];
    }
    __syncthreads();

    float acc[2][4][4];
    #pragma unroll
    for (int mf = 0; mf < 2; ++mf)
        #pragma unroll
        for (int nf = 0; nf < 4; ++nf)
            #pragma unroll
            for (int q = 0; q < 4; ++q) acc[mf][nf][q] = 0.f;

    const int matA = lane >> 3;
    const int arow = (lane & 7) + ((matA & 1) << 3);
    const int acadd = matA >> 1;
    const int brow = (lane & 7) + ((matA >> 1) << 3);
    const int bcadd = matA & 1;

    // fill-phase thread mapping: gaussian pair gp (0..126 even), segment sq (0..7)
    const int gp = (tid & 63) * 2;
    const int sq = tid >> 6;

    #pragma unroll
    for (int ck = 0; ck < 4; ++ck) {
        const int gi = ck * 128 + gp;
        // ---- fill A tile: rows y, this thread does y in [sq*16, sq*16+16) ----
        const float e0 = sEe[gi], e1 = sEe[gi + 1];
        const unsigned long long q01 = f2pack(sQ2[gi], sQ2[gi + 1]);
        {
            const int y0 = sq * 16;
            float d0 = (float)y0 - sPy[gi], d1 = (float)y0 - sPy[gi + 1];
            unsigned long long t = f2pack(__expf(e0 * d0 * d0), __expf(e1 * d1 * d1));
            unsigned long long u = f2pack(__expf(e0 * (2.f * d0 + 1.f)),
                                          __expf(e1 * (2.f * d1 + 1.f)));
            #pragma unroll
            for (int k = 0; k < 16; ++k) {
                float a0, a1;
                f2unpack(t, a0, a1);
                STS32(sb + swzg(y0 + k, gp), pkbf(a0, a1));
                t = f2mul(t, u); u = f2mul(u, q01);
            }
        }
        // ---- fill B tile: rows n = x_local*4 + ch, x_local in [sq*4, sq*4+4) --
        {
            const uint32_t wr2 = pkbf(sWr[gi], sWr[gi + 1]);
            const uint32_t wg2 = pkbf(sWg[gi], sWg[gi + 1]);
            const uint32_t wb2 = pkbf(sWb[gi], sWb[gi + 1]);
            const uint32_t wo2 = pkbf(sWo[gi], sWo[gi + 1]);
            const int xl0 = sq * 4;
            float d0 = (float)(x0b + xl0) - sPx[gi], d1 = (float)(x0b + xl0) - sPx[gi + 1];
            unsigned long long t = f2pack(__expf(e0 * d0 * d0), __expf(e1 * d1 * d1));
            unsigned long long u = f2pack(__expf(e0 * (2.f * d0 + 1.f)),
                                          __expf(e1 * (2.f * d1 + 1.f)));
            #pragma unroll
            for (int k = 0; k < 4; ++k) {
                float a0, a1;
                f2unpack(t, a0, a1);
                uint32_t p = pkbf(a0, a1), v;
                const int rb = (xl0 + k) * 4;
                MULBF2(v, p, wr2); STS32(sb + SM_B_OFF + swzg(rb + 0, gp), v);
                MULBF2(v, p, wg2); STS32(sb + SM_B_OFF + swzg(rb + 1, gp), v);
                MULBF2(v, p, wb2); STS32(sb + SM_B_OFF + swzg(rb + 2, gp), v);
                MULBF2(v, p, wo2); STS32(sb + SM_B_OFF + swzg(rb + 3, gp), v);
                t = f2mul(t, u); u = f2mul(u, q01);
            }
        }
        __syncthreads();

        // ---- MMA: 8 k16-steps over this 128-gaussian chunk ----
        #pragma unroll
        for (int ks = 0; ks < 8; ++ks) {
            const int c0 = ks * 2;
            uint32_t a[2][4];
            #pragma unroll
            for (int mf = 0; mf < 2; ++mf)
                LDSM4(a[mf][0], a[mf][1], a[mf][2], a[mf][3],
                      sb + swz(wm + mf * 16 + arow, c0 + acadd));
            uint32_t b[4][2];
            #pragma unroll
            for (int bq = 0; bq < 2; ++bq) {
                uint32_t r0, r1, r2, r3;
                LDSM4(r0, r1, r2, r3,
                      sb + SM_B_OFF + swz(wn + bq * 16 + brow, c0 + bcadd));
                b[2 * bq][0] = r0; b[2 * bq][1] = r1;
                b[2 * bq + 1][0] = r2; b[2 * bq + 1][1] = r3;
            }
            #pragma unroll
            for (int mf = 0; mf < 2; ++mf)
                #pragma unroll
                for (int nf = 0; nf < 4; ++nf)
                    MMA16816(acc[mf][nf], a[mf], b[nf]);
        }
        __syncthreads();
    }

    // ---- store 128x128 fp32 partial for this split ----
    float* part = &d_Part[blockIdx.y][0][0];
    #pragma unroll
    for (int mf = 0; mf < 2; ++mf) {
        #pragma unroll
        for (int nf = 0; nf < 4; ++nf) {
            int row = wm + mf * 16 + (lane >> 2);
            int cc  = ntb + wn + nf * 8 + (lane & 3) * 2;
            float2 v0 = make_float2(acc[mf][nf][0], acc[mf][nf][1]);
            float2 v1 = make_float2(acc[mf][nf][2], acc[mf][nf][3]);
            *reinterpret_cast<float2*>(part + (size_t)row * 512 + cc)       = v0;
            *reinterpret_cast<float2*>(part + (size_t)(row + 8) * 512 + cc) = v1;
        }
    }
}

// ---------------- finalize: reduce splits, divide, tile-scatter --------------
// channels interleaved: pixel (y,x) -> float4 at d_Part[s][y][4x]
__global__ void __launch_bounds__(256) finalize_kernel(
    float* __restrict__ out, const int* __restrict__ tileHW,
    const int* __restrict__ chunkG, int N)
{
    int p = blockIdx.x * blockDim.x + threadIdx.x;
    if (p >= HH * WW) return;
    int y = p >> 7, x = p & 127;

    float r = 0.f, g = 0.f, b = 0.f, d = 0.f;
    #pragma unroll
    for (int s = 0; s < NSPLIT; ++s) {
        float4 v = *reinterpret_cast<const float4*>(&d_Part[s][y][4 * x]);
        r += v.x; g += v.y; b += v.z; d += v.w;
    }

    int cg = chunkG[0];
    if (cg <= 0 || cg > N) cg = N;
    d += (float)(N / cg) * EPSc;

    int tw = tileHW[0];
    if (tw <= 0 || tw > 128) tw = 64;
    int step = tw * tw;
    int t = p / step;
    int q = p - t * step;

    float inv = __fdividef(1.f, d);
    float* o = out + (size_t)t * 3 * step + q;
    o[0]        = r * inv;
    o[step]     = g * inv;
    o[2 * step] = b * inv;
}

// ---------------- launch -----------------------------------------------------
extern "C" void kernel_launch(void* const* d_in, const int* in_sizes, int n_in,
                              void* d_out, int out_size)
{
    const float* pos = (const float*)d_in[0];
    const float* col = (const float*)d_in[1];
    const float* opa = (const float*)d_in[2];
    const float* sca = (const float*)d_in[3];
    const float* qv  = (const float*)d_in[4];
    const float* tv  = (const float*)d_in[5];
    const int*   tHW = (n_in > 6) ? (const int*)d_in[6] : nullptr;
    const int*   cG  = (n_in > 7) ? (const int*)d_in[7] : nullptr;

    int N = in_sizes[0] / 3;
    if (N > NMAX) N = NMAX;

    cudaFuncSetAttribute(mega_kernel, cudaFuncAttributeMaxDynamicSharedMemorySize, SMEM_TOTAL);
    mega_kernel<<<dim3(4, NSPLIT), 512, SMEM_TOTAL>>>(pos, col, opa, sca, qv, tv);

    finalize_kernel<<<(HH * WW + 255) / 256, 256>>>((float*)d_out, tHW, cG, N);
}

// round 16
// speedup vs baseline: 1.2411x; 1.1065x over previous
#include <cuda_runtime.h>
#include <cuda_bf16.h>
#include <cstdint>

#define HH   128
#define WW   128
#define NMAX 16384
#define NSPLIT 32
#define KSLICE (NMAX / NSPLIT)       /* 512 */
#define FXc 128.0f
#define FYc 128.0f
#define CXc 64.0f
#define CYc 64.0f
#define EPSc 1e-8f

// ---------------- static device scratch (no allocation allowed) -------------
// split-K partials; column layout n = x*4 + ch (channels interleaved)
__device__ float d_Part[NSPLIT][128][512];

// ---------------- PTX helpers ------------------------------------------------
__device__ __forceinline__ uint32_t smem_u32(const void* p) {
    uint32_t a;
    asm("{ .reg .u64 t; cvta.to.shared.u64 t, %1; cvt.u32.u64 %0, t; }" : "=r"(a) : "l"(p));
    return a;
}
#define LDSM4(r0, r1, r2, r3, addr)                                          \
    asm volatile("ldmatrix.sync.aligned.m8n8.x4.shared.b16 {%0,%1,%2,%3}, [%4];" \
        : "=r"(r0), "=r"(r1), "=r"(r2), "=r"(r3) : "r"(addr))
#define MMA16816(d, a, b)                                                    \
    asm volatile("mma.sync.aligned.m16n8k16.row.col.f32.bf16.bf16.f32 "      \
        "{%0,%1,%2,%3}, {%4,%5,%6,%7}, {%8,%9}, {%0,%1,%2,%3};"              \
        : "+f"((d)[0]), "+f"((d)[1]), "+f"((d)[2]), "+f"((d)[3])             \
        : "r"((a)[0]), "r"((a)[1]), "r"((a)[2]), "r"((a)[3]),                \
          "r"((b)[0]), "r"((b)[1]))
#define MULBF2(res, a, b) \
    asm("mul.bf16x2 %0, %1, %2;" : "=r"(res) : "r"(a), "r"(b))
#define STS32(addr, v) \
    asm volatile("st.shared.b32 [%0], %1;" :: "r"(addr), "r"(v))

// packed f32x2 helpers
__device__ __forceinline__ unsigned long long f2pack(float a, float b) {
    unsigned long long r;
    asm("mov.b64 %0, {%1, %2};" : "=l"(r) : "f"(a), "f"(b));
    return r;
}
__device__ __forceinline__ void f2unpack(unsigned long long v, float& a, float& b) {
    asm("mov.b64 {%0, %1}, %2;" : "=f"(a), "=f"(b) : "l"(v));
}
__device__ __forceinline__ unsigned long long f2mul(unsigned long long a, unsigned long long b) {
    unsigned long long r;
    asm("mul.rn.f32x2 %0, %1, %2;" : "=l"(r) : "l"(a), "l"(b));
    return r;
}

// swizzled smem byte offset: 256B rows (128 bf16), granule c = 16B unit 0..15
__device__ __forceinline__ uint32_t swz(int r, int c) {
    return (uint32_t)(r * 256 + ((((c) & 8) | (((c) ^ (r)) & 7)) << 4));
}
// swizzled byte address of the bf16 PAIR starting at even g-index gp in row r
__device__ __forceinline__ uint32_t swzg(int r, int gp) {
    int c = gp >> 3;
    return (uint32_t)(r * 256 + (((c & 8) | ((c ^ r) & 7)) << 4) + ((gp * 2) & 15));
}

__device__ __forceinline__ uint32_t pkbf(float a, float b) {
    __nv_bfloat162 h = __floats2bfloat162_rn(a, b);
    uint32_t u;
    memcpy(&u, &h, 4);
    return u;
}

// ---------------- fused prep+GEMM mega-kernel -------------------------------
// grid = (4 N-tiles, 32 K-splits) = 128 CTAs, 512 threads (16 warps, 4Mx4N).
// N-tile t covers n=[128t,128t+128) = x in [32t,32t+32), channels interleaved.
#define SM_B_OFF 32768
#define SMEM_TOTAL 65536

__global__ void __launch_bounds__(512, 1) mega_kernel(
    const float* __restrict__ pos, const float* __restrict__ col,
    const float* __restrict__ opa, const float* __restrict__ sca,
    const float* __restrict__ qv,  const float* __restrict__ tv)
{
    __shared__ float sPx[512], sPy[512], sEe[512], sQ2[512];
    __shared__ float sWr[512], sWg[512], sWb[512], sWo[512];
    extern __shared__ char smem[];
    const uint32_t sb = smem_u32(smem);
    const int tid  = threadIdx.x;
    const int lane = tid & 31;
    const int wid  = tid >> 5;
    const int wm   = (wid & 3) * 32;
    const int wn   = (wid >> 2) * 32;
    const int ntb  = blockIdx.x * 128;   // global n base
    const int x0b  = blockIdx.x * 32;    // global x base for this N-tile
    const int g0   = blockIdx.y * KSLICE;

    // ---- params: one gaussian per thread ----
    {
        int g = g0 + tid;
        float qw = qv[0], qx = qv[1], qy = qv[2], qz = qv[3];
        float qn = rsqrtf(qw * qw + qx * qx + qy * qy + qz * qz);
        qw *= qn; qx *= qn; qy *= qn; qz *= qn;
        float r00 = 1.f - 2.f * (qy * qy + qz * qz), r01 = 2.f * (qx * qy - qz * qw), r02 = 2.f * (qx * qz + qy * qw);
        float r10 = 2.f * (qx * qy + qz * qw), r11 = 1.f - 2.f * (qx * qx + qz * qz), r12 = 2.f * (qy * qz - qx * qw);
        float r20 = 2.f * (qx * qz - qy * qw), r21 = 2.f * (qy * qz + qx * qw), r22 = 1.f - 2.f * (qx * qx + qy * qy);

        float p0 = pos[3 * g + 0], p1 = pos[3 * g + 1], p2 = pos[3 * g + 2];
        float cx = r00 * p0 + r01 * p1 + r02 * p2 + tv[0];
        float cy = r10 * p0 + r11 * p1 + r12 * p2 + tv[1];
        float cz = r20 * p0 + r21 * p1 + r22 * p2 + tv[2];
        float invz = __fdividef(1.f, cz);
        sPx[tid] = cx * invz * FXc + CXc;
        sPy[tid] = cy * invz * FYc + CYc;
        float s = sca[g];
        float e = -0.5f * __fdividef(1.f, s * s);
        sEe[tid] = e;
        sQ2[tid] = __expf(2.f * e);
        float o = opa[g];
        sWo[tid] = o;
        sWr[tid] = o * col[3 * g + 0];
        sWg[tid] = o * col[3 * g + 1];
        sWb[tid] = o * col[3 * g + 2];
    }
    __syncthreads();

    float acc[2][4][4];
    #pragma unroll
    for (int mf = 0; mf < 2; ++mf)
        #pragma unroll
        for (int nf = 0; nf < 4; ++nf)
            #pragma unroll
            for (int q = 0; q < 4; ++q) acc[mf][nf][q] = 0.f;

    const int matA = lane >> 3;
    const int arow = (lane & 7) + ((matA & 1) << 3);
    const int acadd = matA >> 1;
    const int brow = (lane & 7) + ((matA >> 1) << 3);
    const int bcadd = matA & 1;

    // fill-phase thread mapping: gaussian pair gp (0..126 even), segment sq (0..7)
    const int gp = (tid & 63) * 2;
    const int sq = tid >> 6;

    #pragma unroll
    for (int ck = 0; ck < 4; ++ck) {
        const int gi = ck * 128 + gp;
        const float e0 = sEe[gi], e1 = sEe[gi + 1];
        const unsigned long long q01 = f2pack(sQ2[gi], sQ2[gi + 1]);
        // ---- fill A tile: rows y in [sq*16, sq*16+16) ----
        {
            const int y0 = sq * 16;
            float d0 = (float)y0 - sPy[gi], d1 = (float)y0 - sPy[gi + 1];
            unsigned long long t = f2pack(__expf(e0 * d0 * d0), __expf(e1 * d1 * d1));
            unsigned long long u = f2pack(__expf(e0 * (2.f * d0 + 1.f)),
                                          __expf(e1 * (2.f * d1 + 1.f)));
            #pragma unroll
            for (int k = 0; k < 16; ++k) {
                float a0, a1;
                f2unpack(t, a0, a1);
                STS32(sb + swzg(y0 + k, gp), pkbf(a0, a1));
                t = f2mul(t, u); u = f2mul(u, q01);
            }
        }
        // ---- fill B tile: rows n = x_local*4 + ch, x_local in [sq*4, sq*4+4) --
        {
            const uint32_t wr2 = pkbf(sWr[gi], sWr[gi + 1]);
            const uint32_t wg2 = pkbf(sWg[gi], sWg[gi + 1]);
            const uint32_t wb2 = pkbf(sWb[gi], sWb[gi + 1]);
            const uint32_t wo2 = pkbf(sWo[gi], sWo[gi + 1]);
            const int xl0 = sq * 4;
            float d0 = (float)(x0b + xl0) - sPx[gi], d1 = (float)(x0b + xl0) - sPx[gi + 1];
            unsigned long long t = f2pack(__expf(e0 * d0 * d0), __expf(e1 * d1 * d1));
            unsigned long long u = f2pack(__expf(e0 * (2.f * d0 + 1.f)),
                                          __expf(e1 * (2.f * d1 + 1.f)));
            #pragma unroll
            for (int k = 0; k < 4; ++k) {
                float a0, a1;
                f2unpack(t, a0, a1);
                uint32_t p = pkbf(a0, a1), v;
                const int rb = (xl0 + k) * 4;
                MULBF2(v, p, wr2); STS32(sb + SM_B_OFF + swzg(rb + 0, gp), v);
                MULBF2(v, p, wg2); STS32(sb + SM_B_OFF + swzg(rb + 1, gp), v);
                MULBF2(v, p, wb2); STS32(sb + SM_B_OFF + swzg(rb + 2, gp), v);
                MULBF2(v, p, wo2); STS32(sb + SM_B_OFF + swzg(rb + 3, gp), v);
                t = f2mul(t, u); u = f2mul(u, q01);
            }
        }
        __syncthreads();

        // ---- MMA: 8 k16-steps over this 128-gaussian chunk ----
        #pragma unroll
        for (int ks = 0; ks < 8; ++ks) {
            const int c0 = ks * 2;
            uint32_t a[2][4];
            #pragma unroll
            for (int mf = 0; mf < 2; ++mf)
                LDSM4(a[mf][0], a[mf][1], a[mf][2], a[mf][3],
                      sb + swz(wm + mf * 16 + arow, c0 + acadd));
            uint32_t b[4][2];
            #pragma unroll
            for (int bq = 0; bq < 2; ++bq) {
                uint32_t r0, r1, r2, r3;
                LDSM4(r0, r1, r2, r3,
                      sb + SM_B_OFF + swz(wn + bq * 16 + brow, c0 + bcadd));
                b[2 * bq][0] = r0; b[2 * bq][1] = r1;
                b[2 * bq + 1][0] = r2; b[2 * bq + 1][1] = r3;
            }
            #pragma unroll
            for (int mf = 0; mf < 2; ++mf)
                #pragma unroll
                for (int nf = 0; nf < 4; ++nf)
                    MMA16816(acc[mf][nf], a[mf], b[nf]);
        }
        __syncthreads();
    }

    // ---- store 128x128 fp32 partial for this split ----
    float* part = &d_Part[blockIdx.y][0][0];
    #pragma unroll
    for (int mf = 0; mf < 2; ++mf) {
        #pragma unroll
        for (int nf = 0; nf < 4; ++nf) {
            int row = wm + mf * 16 + (lane >> 2);
            int cc  = ntb + wn + nf * 8 + (lane & 3) * 2;
            float2 v0 = make_float2(acc[mf][nf][0], acc[mf][nf][1]);
            float2 v1 = make_float2(acc[mf][nf][2], acc[mf][nf][3]);
            *reinterpret_cast<float2*>(part + (size_t)row * 512 + cc)       = v0;
            *reinterpret_cast<float2*>(part + (size_t)(row + 8) * 512 + cc) = v1;
        }
    }
}

// ---------------- finalize v2: 4 threads/pixel + shfl tree ------------------
// 128 blocks x 512 threads = 65536 threads. Thread j: pixel p=j>>2,
// quarter q=j&3, sums splits [8q, 8q+8), then xor-shuffle reduce over q.
__global__ void __launch_bounds__(512) finalize_kernel(
    float* __restrict__ out, const int* __restrict__ tileHW,
    const int* __restrict__ chunkG, int N)
{
    int j = blockIdx.x * 512 + threadIdx.x;
    int p = j >> 2, q = j & 3;
    int y = p >> 7, x = p & 127;

    float r = 0.f, g = 0.f, b = 0.f, d = 0.f;
    #pragma unroll
    for (int i = 0; i < 8; ++i) {
        float4 v = *reinterpret_cast<const float4*>(&d_Part[q * 8 + i][y][4 * x]);
        r += v.x; g += v.y; b += v.z; d += v.w;
    }

    // combine the 4 quarter-sums (lanes differing in bits 0,1)
    r += __shfl_xor_sync(0xFFFFFFFFu, r, 1);
    g += __shfl_xor_sync(0xFFFFFFFFu, g, 1);
    b += __shfl_xor_sync(0xFFFFFFFFu, b, 1);
    d += __shfl_xor_sync(0xFFFFFFFFu, d, 1);
    r += __shfl_xor_sync(0xFFFFFFFFu, r, 2);
    g += __shfl_xor_sync(0xFFFFFFFFu, g, 2);
    b += __shfl_xor_sync(0xFFFFFFFFu, b, 2);
    d += __shfl_xor_sync(0xFFFFFFFFu, d, 2);

    if (q == 0) {
        int cg = chunkG[0];
        if (cg <= 0 || cg > N) cg = N;
        d += (float)(N / cg) * EPSc;

        int tw = tileHW[0];
        if (tw <= 0 || tw > 128) tw = 64;
        int step = tw * tw;
        int t = p / step;
        int qq = p - t * step;

        float inv = __fdividef(1.f, d);
        float* o = out + (size_t)t * 3 * step + qq;
        o[0]        = r * inv;
        o[step]     = g * inv;
        o[2 * step] = b * inv;
    }
}

// ---------------- launch -----------------------------------------------------
extern "C" void kernel_launch(void* const* d_in, const int* in_sizes, int n_in,
                              void* d_out, int out_size)
{
    const float* pos = (const float*)d_in[0];
    const float* col = (const float*)d_in[1];
    const float* opa = (const float*)d_in[2];
    const float* sca = (const float*)d_in[3];
    const float* qv  = (const float*)d_in[4];
    const float* tv  = (const float*)d_in[5];
    const int*   tHW = (n_in > 6) ? (const int*)d_in[6] : nullptr;
    const int*   cG  = (n_in > 7) ? (const int*)d_in[7] : nullptr;

    int N = in_sizes[0] / 3;
    if (N > NMAX) N = NMAX;

    cudaFuncSetAttribute(mega_kernel, cudaFuncAttributeMaxDynamicSharedMemorySize, SMEM_TOTAL);
    mega_kernel<<<dim3(4, NSPLIT), 512, SMEM_TOTAL>>>(pos, col, opa, sca, qv, tv);

    finalize_kernel<<<(HH * WW * 4) / 512, 512>>>((float*)d_out, tHW, cG, N);
}